// round 11
// baseline (speedup 1.0000x reference)
#include <cuda_runtime.h>
#include <cstdint>

// Problem constants
constexpr int B_  = 32;
constexpr int T_  = 1024;
constexpr int F_  = 512;
constexpr int H_  = 512;
constexpr int G4H = 2048;   // 4*H

#define NB 128   // recurrence blocks = 16 clusters x 8 CTAs
#define NT 256   // 8 warps: warp w owns k-slice [64w, 64w+64)
#define KW 64    // k per warp
#define CLS 8    // cluster size
#define SLICE_BYTES 8192           // 64 k x 32 b x 4B
#define HTOT_BYTES  65536          // full h

// ---------------- device scratch ----------------
__device__ float g_z0t[(size_t)T_ * G4H * B_];   // [t][gatecol][b]
__device__ float g_hT[2][H_ * B_];               // ping-pong h, transposed [k][b]
__device__ unsigned g_root;                      // monotonic flat barrier counter

// ---------------- f32x2 + sync helpers ----------------
__device__ __forceinline__ unsigned long long pack2(float x, float y) {
    unsigned long long r;
    asm("mov.b64 %0, {%1, %2};" : "=l"(r) : "f"(x), "f"(y));
    return r;
}
__device__ __forceinline__ unsigned long long fma2(unsigned long long a,
                                                   unsigned long long b,
                                                   unsigned long long c) {
    unsigned long long d;
    asm("fma.rn.f32x2 %0, %1, %2, %3;" : "=l"(d) : "l"(a), "l"(b), "l"(c));
    return d;
}
__device__ __forceinline__ unsigned long long add2(unsigned long long a,
                                                   unsigned long long b) {
    unsigned long long d;
    asm("add.rn.f32x2 %0, %1, %2;" : "=l"(d) : "l"(a), "l"(b));
    return d;
}
__device__ __forceinline__ float2 unpack2(unsigned long long v) {
    float2 f;
    asm("mov.b64 {%0, %1}, %2;" : "=f"(f.x), "=f"(f.y) : "l"(v));
    return f;
}
__device__ __forceinline__ unsigned ld_acq(const unsigned* p) {
    unsigned v;
    asm volatile("ld.acquire.gpu.global.u32 %0, [%1];"
                 : "=r"(v) : "l"(p) : "memory");
    return v;
}
__device__ __forceinline__ void red_rel_add1(unsigned* p) {
    asm volatile("red.release.gpu.global.add.u32 [%0], 1;"
                 :: "l"(p) : "memory");
}
__device__ __forceinline__ float sigf(float x) {
    return 1.f / (1.f + __expf(-x));
}
__device__ __forceinline__ float tanh_fast(float x) {
    return 2.f / (1.f + __expf(-2.f * x)) - 1.f;
}
__device__ __forceinline__ unsigned smem_u32(const void* p) {
    return (unsigned)__cvta_generic_to_shared(p);
}
__device__ __forceinline__ unsigned ctarank() {
    unsigned r;
    asm("mov.u32 %0, %%cluster_ctarank;" : "=r"(r));
    return r;
}
__device__ __forceinline__ void mbar_init(unsigned mbar, unsigned cnt) {
    asm volatile("mbarrier.init.shared.b64 [%0], %1;"
                 :: "r"(mbar), "r"(cnt) : "memory");
}
__device__ __forceinline__ void mbar_expect_tx(unsigned mbar, unsigned bytes) {
    asm volatile("mbarrier.arrive.expect_tx.shared.b64 _, [%0], %1;"
                 :: "r"(mbar), "r"(bytes) : "memory");
}
__device__ __forceinline__ void mbar_wait(unsigned mbar, unsigned parity) {
    asm volatile(
        "{\n\t"
        ".reg .pred P;\n\t"
        "W%=:\n\t"
        "mbarrier.try_wait.parity.acquire.cta.shared::cta.b64 P, [%0], %1, 0x989680;\n\t"
        "@!P bra W%=;\n\t"
        "}"
        :: "r"(mbar), "r"(parity) : "memory");
}
// Non-tensor bulk copy, global->shared::cluster, multicast to all 8 CTAs.
__device__ __forceinline__ void bulk_mcast(unsigned dst_smem, const void* src,
                                           unsigned bytes, unsigned mbar,
                                           unsigned short mask) {
    asm volatile(
        "cp.async.bulk.shared::cluster.global.mbarrier::complete_tx::bytes"
        ".multicast::cluster [%0], [%1], %2, [%3], %4;"
        :: "r"(dst_smem), "l"(src), "r"(bytes), "r"(mbar), "h"(mask)
        : "memory");
}
__device__ __forceinline__ void cluster_sync() {
    asm volatile("barrier.cluster.arrive.aligned;" ::: "memory");
    asm volatile("barrier.cluster.wait.aligned;" ::: "memory");
}

// ---------------- GEMM (f32x2, register double-buffered) + embedded init ----------------
// Exact round-9 version (validated fastest).
__global__ void __launch_bounds__(256) gemm_xwi(const float* __restrict__ x,
                                                const float* __restrict__ Wi,
                                                const float* __restrict__ bias,
                                                const float* __restrict__ h0) {
    __shared__ float As[2][16][64];
    __shared__ float Bs[2][16][64];
    const int tid = threadIdx.x;

    if (blockIdx.x == 0 && blockIdx.y == 0) {
        for (int i = tid; i < H_ * B_; i += 256) {
            int b = i / H_;
            int k = i - b * H_;
            g_hT[0][k * B_ + b] = h0[i];
        }
        if (tid == 0) g_root = 0;
    }

    const int tm = tid >> 4;
    const int tn = tid & 15;
    const int row0 = blockIdx.y * 64;
    const int col0 = blockIdx.x * 64;

    unsigned long long acc[4][2] = {};

    const int ar  = tid >> 2;
    const int akq = (tid & 3) * 4;
    const int br  = tid >> 4;
    const int bnq = (tid & 15) * 4;

    const float* xp = &x[(size_t)(row0 + ar) * F_ + akq];
    const float* wp = &Wi[(size_t)br * G4H + col0 + bnq];

    float4 av = *(const float4*)xp;
    float4 bv = *(const float4*)wp;

    for (int kt = 0; kt < 32; kt++) {
        const int cur = kt & 1;
        As[cur][akq + 0][ar] = av.x;
        As[cur][akq + 1][ar] = av.y;
        As[cur][akq + 2][ar] = av.z;
        As[cur][akq + 3][ar] = av.w;
        *(float4*)&Bs[cur][br][bnq] = bv;
        __syncthreads();
        if (kt < 31) {
            av = *(const float4*)(xp + (kt + 1) * 16);
            bv = *(const float4*)(wp + (size_t)(kt + 1) * 16 * G4H);
        }
#pragma unroll
        for (int k = 0; k < 16; k++) {
            float4 a = *(const float4*)&As[cur][k][tm * 4];
            const unsigned long long* bp =
                (const unsigned long long*)&Bs[cur][k][tn * 4];
            unsigned long long b0 = bp[0], b1 = bp[1];
            unsigned long long a0 = pack2(a.x, a.x);
            unsigned long long a1 = pack2(a.y, a.y);
            unsigned long long a2 = pack2(a.z, a.z);
            unsigned long long a3 = pack2(a.w, a.w);
            acc[0][0] = fma2(a0, b0, acc[0][0]); acc[0][1] = fma2(a0, b1, acc[0][1]);
            acc[1][0] = fma2(a1, b0, acc[1][0]); acc[1][1] = fma2(a1, b1, acc[1][1]);
            acc[2][0] = fma2(a2, b0, acc[2][0]); acc[2][1] = fma2(a2, b1, acc[2][1]);
            acc[3][0] = fma2(a3, b0, acc[3][0]); acc[3][1] = fma2(a3, b1, acc[3][1]);
        }
    }

#pragma unroll
    for (int i = 0; i < 4; i++) {
        int r  = row0 + tm * 4 + i;
        int t  = r & (T_ - 1);
        int bb = r >> 10;
#pragma unroll
        for (int j = 0; j < 2; j++) {
            float2 v = unpack2(acc[i][j]);
            int c0c = col0 + tn * 4 + j * 2;
            g_z0t[((size_t)t * G4H + c0c + 0) * B_ + bb] = v.x + bias[c0c + 0];
            g_z0t[((size_t)t * G4H + c0c + 1) * B_ + bb] = v.y + bias[c0c + 1];
        }
    }
}

// ---------------- recurrence: cluster-multicast h distribution ----------------
// 16 clusters x 8 CTAs. Each CTA rank r multicasts h-slice r (8KB) to all 8
// CTAs' smem; mbarrier expect_tx = 64KB aggregates the cooperative slices.
// Global step ordering still via the flat monotonic g_root barrier.
__global__ void __launch_bounds__(NT, 1) __cluster_dims__(CLS, 1, 1)
lstm_rec(const float* __restrict__ c0,
         const float* __restrict__ Wh,
         float* __restrict__ out) {
    extern __shared__ unsigned char dsm[];
    unsigned long long* Wsu = (unsigned long long*)dsm;          // 32KB
    float* hs = (float*)(Wsu + 512 * 8);                         // 64KB [k*32+b]
    unsigned long long* red = (unsigned long long*)(hs + 512*32);// 16KB
    float* hout = (float*)(red + 8 * 8 * 32);                    // 512B
    unsigned long long* mbar_st = (unsigned long long*)(hout + 128);
    const unsigned mbar = smem_u32(mbar_st);
    const unsigned hs_sa = smem_u32(hs);

    const int tid = threadIdx.x;
    const int w   = tid >> 5;
    const int b   = tid & 31;
    const unsigned rank = ctarank();

    if (tid == 0) mbar_init(mbar, 1);

    // Stage Wh slice once: (wi,wf),(wg,wo) pairs per (k, col nl).
    for (int idx = tid; idx < H_ * 4; idx += NT) {
        int k  = idx >> 2;
        int n2 = idx & 3;
        int cb = blockIdx.x * 4 + n2;
        float wi = Wh[(size_t)k * G4H + 0 * H_ + cb];
        float wf = Wh[(size_t)k * G4H + 1 * H_ + cb];
        float wg = Wh[(size_t)k * G4H + 2 * H_ + cb];
        float wo = Wh[(size_t)k * G4H + 3 * H_ + cb];
        Wsu[k * 8 + n2 * 2 + 0] = pack2(wi, wf);
        Wsu[k * 8 + n2 * 2 + 1] = pack2(wg, wo);
    }

    // Epilogue-mapped state (tid < 128): nl = tid>>5, bb = tid&31.
    const int nl = tid >> 5;
    const int bb = tid & 31;
    const int ncol = blockIdx.x * 4 + nl;
    float c = (tid < 128) ? c0[(size_t)bb * H_ + ncol] : 0.f;

    float* c_fin = out;
    float* h_fin = out + B_ * H_;
    float* hist  = out + 2 * B_ * H_;            // [b][t][h]

    __syncthreads();
    cluster_sync();          // all CTAs' mbarriers initialized before multicast

    // z prefetch for t = 0.
    float z0 = 0.f, z1 = 0.f, z2 = 0.f, z3 = 0.f;
    if (tid < 128) {
        size_t zb = ((size_t)0 * G4H + ncol) * B_ + bb;
        z0 = __ldcs(&g_z0t[zb + (size_t)0 * H_ * B_]);
        z1 = __ldcs(&g_z0t[zb + (size_t)1 * H_ * B_]);
        z2 = __ldcs(&g_z0t[zb + (size_t)2 * H_ * B_]);
        z3 = __ldcs(&g_z0t[zb + (size_t)3 * H_ * B_]);
    }

    for (int t = 0; t < T_; t++) {
        float* hdst = g_hT[(t + 1) & 1];

        // ---- leader: global-order wait, then cooperative multicast slice ----
        if (tid == 0) {
            if (t > 0) {
                unsigned target = 128u * (unsigned)t;
                while (ld_acq(&g_root) < target) { }
            }
            mbar_expect_tx(mbar, HTOT_BYTES);
            const void* src = (const char*)g_hT[t & 1] + rank * SLICE_BYTES;
            bulk_mcast(hs_sa + rank * SLICE_BYTES, src, SLICE_BYTES, mbar,
                       (unsigned short)0xFF);
        }

        // ---- all threads: wait for the full 64KB h tile (8 slices) ----
        mbar_wait(mbar, (unsigned)(t & 1));

        // ---- compute: 64 k, 16 FMA2s each (4 cols x 4 gates) ----
        unsigned long long a0 = 0, a1 = 0, a2 = 0, a3 = 0;
        unsigned long long a4 = 0, a5 = 0, a6 = 0, a7 = 0;
        const float* hp = hs + (size_t)w * KW * 32 + b;
        const ulonglong2* wp = (const ulonglong2*)(Wsu + (size_t)w * KW * 8);
#pragma unroll 4
        for (int kk = 0; kk < KW; kk++) {
            float hv = hp[kk * 32];
            unsigned long long hh = pack2(hv, hv);
            ulonglong2 w01 = wp[kk * 4 + 0];
            ulonglong2 w23 = wp[kk * 4 + 1];
            ulonglong2 w45 = wp[kk * 4 + 2];
            ulonglong2 w67 = wp[kk * 4 + 3];
            a0 = fma2(hh, w01.x, a0); a1 = fma2(hh, w01.y, a1);
            a2 = fma2(hh, w23.x, a2); a3 = fma2(hh, w23.y, a3);
            a4 = fma2(hh, w45.x, a4); a5 = fma2(hh, w45.y, a5);
            a6 = fma2(hh, w67.x, a6); a7 = fma2(hh, w67.y, a7);
        }

        // ---- publish partials: red[j][w][b] (conflict-free) ----
        red[0 * 256 + w * 32 + b] = a0;
        red[1 * 256 + w * 32 + b] = a1;
        red[2 * 256 + w * 32 + b] = a2;
        red[3 * 256 + w * 32 + b] = a3;
        red[4 * 256 + w * 32 + b] = a4;
        red[5 * 256 + w * 32 + b] = a5;
        red[6 * 256 + w * 32 + b] = a6;
        red[7 * 256 + w * 32 + b] = a7;
        __syncthreads();

        // ---- reduce + fast gates (epilogue threads, col nl / batch bb) ----
        float h = 0.f;
        if (tid < 128) {
            const unsigned long long* rif = red + (nl * 2 + 0) * 256 + bb;
            const unsigned long long* rgo = red + (nl * 2 + 1) * 256 + bb;
            unsigned long long aif = pack2(z0, z1);
            unsigned long long ago = pack2(z2, z3);
#pragma unroll
            for (int ww = 0; ww < 8; ww++) {
                aif = add2(aif, rif[ww * 32]);
                ago = add2(ago, rgo[ww * 32]);
            }
            float2 zif = unpack2(aif);
            float2 zgo = unpack2(ago);

            float ig = sigf(zif.x);
            float fg = sigf(zif.y);
            float gg = tanh_fast(zgo.x);
            float og = sigf(zgo.y);
            c = fg * c + ig * gg;
            h = og * tanh_fast(c);

            __stcg(&hdst[ncol * B_ + bb], h);    // publish via L2 (coalesced)
            hout[bb * 4 + nl] = h;
        }
        __syncthreads();   // hs reads + hout writes done -> safe to arrive

        // ---- arrive: our columns of h(t+1) are published ----
        if (tid == 0) red_rel_add1(&g_root);

        // ---- off-critical-path tail: hist write + next z prefetch ----
        if (tid < 32) {
            float4 hv4 = ((const float4*)hout)[tid];
            *(float4*)&hist[((size_t)tid * T_ + t) * H_ + blockIdx.x * 4] = hv4;
        }
        if (tid < 128) {
            if (t == T_ - 1) {
                c_fin[bb * H_ + ncol] = c;
                h_fin[bb * H_ + ncol] = h;
            } else {
                size_t zb = ((size_t)(t + 1) * G4H + ncol) * B_ + bb;
                z0 = __ldcs(&g_z0t[zb + (size_t)0 * H_ * B_]);
                z1 = __ldcs(&g_z0t[zb + (size_t)1 * H_ * B_]);
                z2 = __ldcs(&g_z0t[zb + (size_t)2 * H_ * B_]);
                z3 = __ldcs(&g_z0t[zb + (size_t)3 * H_ * B_]);
            }
        }
    }

    cluster_sync();          // no CTA exits while peers' multicasts in flight
}

// ---------------- launch ----------------
extern "C" void kernel_launch(void* const* d_in, const int* in_sizes, int n_in,
                              void* d_out, int out_size) {
    const float* x    = (const float*)d_in[0];
    const float* h0   = (const float*)d_in[1];
    const float* c0   = (const float*)d_in[2];
    const float* Wi   = (const float*)d_in[3];
    const float* Wh   = (const float*)d_in[4];
    const float* bias = (const float*)d_in[5];
    float* out = (float*)d_out;

    // 32KB (Wsu) + 64KB (hs) + 16KB (red) + 512B (hout) + 16B (mbar)
    const int rec_smem = 512 * 8 * 8 + 512 * 32 * 4 + 8 * 8 * 32 * 8
                       + 128 * 4 + 16;
    cudaFuncSetAttribute(lstm_rec, cudaFuncAttributeMaxDynamicSharedMemorySize,
                         rec_smem);

    dim3 ggrid(G4H / 64, (B_ * T_) / 64);
    gemm_xwi<<<ggrid, 256>>>(x, Wi, bias, h0);

    lstm_rec<<<NB, NT, rec_smem>>>(c0, Wh, out);
}

// round 12
// speedup vs baseline: 2.1191x; 2.1191x over previous
#include <cuda_runtime.h>
#include <cstdint>

// Problem constants
constexpr int B_  = 32;
constexpr int T_  = 1024;
constexpr int F_  = 512;
constexpr int H_  = 512;
constexpr int G4H = 2048;   // 4*H

// Recurrence: 4 independent batch groups x 32 blocks. Block handles 16 h-cols
// (64 gate-cols) for its group's 8 batch elements.
#define NB 128
#define NT 256
#define NG 4     // groups
#define JB 32    // blocks per group
#define BG 8     // batch per group
#define HC 16    // h-cols per block

// ---------------- device scratch ----------------
__device__ float g_z0t[(size_t)T_ * G4H * B_];     // [t][gatecol][b]
__device__ float g_gh[NG][2][H_ * BG];             // per-group h ping-pong [k][b]
__device__ unsigned g_rootv[NG * 32];              // per-group barrier counters

// ---------------- f32x2 + sync helpers ----------------
__device__ __forceinline__ unsigned long long pack2(float x, float y) {
    unsigned long long r;
    asm("mov.b64 %0, {%1, %2};" : "=l"(r) : "f"(x), "f"(y));
    return r;
}
__device__ __forceinline__ unsigned long long fma2(unsigned long long a,
                                                   unsigned long long b,
                                                   unsigned long long c) {
    unsigned long long d;
    asm("fma.rn.f32x2 %0, %1, %2, %3;" : "=l"(d) : "l"(a), "l"(b), "l"(c));
    return d;
}
__device__ __forceinline__ unsigned long long add2(unsigned long long a,
                                                   unsigned long long b) {
    unsigned long long d;
    asm("add.rn.f32x2 %0, %1, %2;" : "=l"(d) : "l"(a), "l"(b));
    return d;
}
__device__ __forceinline__ float2 unpack2(unsigned long long v) {
    float2 f;
    asm("mov.b64 {%0, %1}, %2;" : "=f"(f.x), "=f"(f.y) : "l"(v));
    return f;
}
__device__ __forceinline__ unsigned ld_acq(const unsigned* p) {
    unsigned v;
    asm volatile("ld.acquire.gpu.global.u32 %0, [%1];"
                 : "=r"(v) : "l"(p) : "memory");
    return v;
}
__device__ __forceinline__ void red_rel_add1(unsigned* p) {
    asm volatile("red.release.gpu.global.add.u32 [%0], 1;"
                 :: "l"(p) : "memory");
}
__device__ __forceinline__ float sigf(float x) {
    return 1.f / (1.f + __expf(-x));
}
__device__ __forceinline__ float tanh_fast(float x) {
    return 2.f / (1.f + __expf(-2.f * x)) - 1.f;
}

// ---------------- GEMM (f32x2, register double-buffered) + embedded init ----------------
// Exact round-9 version (validated fastest); init extended for group state.
__global__ void __launch_bounds__(256) gemm_xwi(const float* __restrict__ x,
                                                const float* __restrict__ Wi,
                                                const float* __restrict__ bias,
                                                const float* __restrict__ h0) {
    __shared__ float As[2][16][64];
    __shared__ float Bs[2][16][64];
    const int tid = threadIdx.x;

    if (blockIdx.x == 0 && blockIdx.y == 0) {
        // init per-group transposed h0: g_gh[g][0][k*8 + b] = h0[(g*8+b)*512 + k]
        for (int i = tid; i < NG * H_ * BG; i += 256) {
            int g   = i >> 12;
            int rem = i & 4095;
            int k   = rem >> 3;
            int b   = rem & 7;
            g_gh[g][0][rem] = h0[(size_t)(g * BG + b) * H_ + k];
        }
        if (tid < NG) g_rootv[tid * 32] = 0;
    }

    const int tm = tid >> 4;
    const int tn = tid & 15;
    const int row0 = blockIdx.y * 64;
    const int col0 = blockIdx.x * 64;

    unsigned long long acc[4][2] = {};

    const int ar  = tid >> 2;
    const int akq = (tid & 3) * 4;
    const int br  = tid >> 4;
    const int bnq = (tid & 15) * 4;

    const float* xp = &x[(size_t)(row0 + ar) * F_ + akq];
    const float* wp = &Wi[(size_t)br * G4H + col0 + bnq];

    float4 av = *(const float4*)xp;
    float4 bv = *(const float4*)wp;

    for (int kt = 0; kt < 32; kt++) {
        const int cur = kt & 1;
        As[cur][akq + 0][ar] = av.x;
        As[cur][akq + 1][ar] = av.y;
        As[cur][akq + 2][ar] = av.z;
        As[cur][akq + 3][ar] = av.w;
        *(float4*)&Bs[cur][br][bnq] = bv;
        __syncthreads();
        if (kt < 31) {
            av = *(const float4*)(xp + (kt + 1) * 16);
            bv = *(const float4*)(wp + (size_t)(kt + 1) * 16 * G4H);
        }
#pragma unroll
        for (int k = 0; k < 16; k++) {
            float4 a = *(const float4*)&As[cur][k][tm * 4];
            const unsigned long long* bp =
                (const unsigned long long*)&Bs[cur][k][tn * 4];
            unsigned long long b0 = bp[0], b1 = bp[1];
            unsigned long long a0 = pack2(a.x, a.x);
            unsigned long long a1 = pack2(a.y, a.y);
            unsigned long long a2 = pack2(a.z, a.z);
            unsigned long long a3 = pack2(a.w, a.w);
            acc[0][0] = fma2(a0, b0, acc[0][0]); acc[0][1] = fma2(a0, b1, acc[0][1]);
            acc[1][0] = fma2(a1, b0, acc[1][0]); acc[1][1] = fma2(a1, b1, acc[1][1]);
            acc[2][0] = fma2(a2, b0, acc[2][0]); acc[2][1] = fma2(a2, b1, acc[2][1]);
            acc[3][0] = fma2(a3, b0, acc[3][0]); acc[3][1] = fma2(a3, b1, acc[3][1]);
        }
    }

#pragma unroll
    for (int i = 0; i < 4; i++) {
        int r  = row0 + tm * 4 + i;
        int t  = r & (T_ - 1);
        int bb = r >> 10;
#pragma unroll
        for (int j = 0; j < 2; j++) {
            float2 v = unpack2(acc[i][j]);
            int c0c = col0 + tn * 4 + j * 2;
            g_z0t[((size_t)t * G4H + c0c + 0) * B_ + bb] = v.x + bias[c0c + 0];
            g_z0t[((size_t)t * G4H + c0c + 1) * B_ + bb] = v.y + bias[c0c + 1];
        }
    }
}

// ---------------- recurrence: 4 independent batch groups ----------------
// blockIdx.x = j*4 + g (same-j blocks adjacent -> share Wh slice in L2).
// Compute: warp = k-split ks (64 k); lane = (hcol 0..15, pair 0..1).
// Thread accumulates its (hcol, gate-pair) over 8 batch elements.
// Epilogue (tid<128): b = tid>>4, hcol = tid&15.
// Dynamic smem: Wsu 128KB | hdup 32KB (h,h pairs) | red 16KB | hout 512B.
__global__ void __launch_bounds__(NT, 1) lstm_rec(const float* __restrict__ c0,
                                                  const float* __restrict__ Wh,
                                                  float* __restrict__ out) {
    extern __shared__ unsigned char dsm[];
    unsigned long long* Wsu  = (unsigned long long*)dsm;           // [k*32+hc*2+pr]
    unsigned long long* hdup = Wsu + 512 * 32;                     // [k*8+b] (h,h)
    unsigned long long* red  = hdup + 512 * 8;                     // [ks*256+b*32+lane]
    float* hout = (float*)(red + 8 * 256);                         // [b*16+hc]

    const int tid  = threadIdx.x;
    const int ks   = tid >> 5;                 // warp = k-split
    const int lane = tid & 31;
    const int g    = blockIdx.x & 3;           // group
    const int j    = blockIdx.x >> 2;          // block within group (0..31)

    // Stage this block's Wh slice ONCE: 512 k x 16 hcols x (if),(go) pairs.
    for (int idx = tid; idx < 512 * HC; idx += NT) {
        int k  = idx >> 4;
        int hc = idx & 15;
        int cb = j * HC + hc;
        const float* wr = &Wh[(size_t)k * G4H + cb];
        Wsu[k * 32 + hc * 2 + 0] = pack2(wr[0 * H_], wr[1 * H_]);
        Wsu[k * 32 + hc * 2 + 1] = pack2(wr[2 * H_], wr[3 * H_]);
    }

    // Epilogue-mapped state (tid < 128): b = tid>>4 (0..7), hc = tid&15.
    const int eb = tid >> 4;
    const int ec = tid & 15;
    const int hg = j * HC + ec;                // global h column
    const int bg = g * BG + eb;                // global batch index
    float c = (tid < 128) ? c0[(size_t)bg * H_ + hg] : 0.f;

    float* c_fin = out;
    float* h_fin = out + B_ * H_;
    float* hist  = out + 2 * B_ * H_;          // [b][t][h]

    unsigned* bar = &g_rootv[g * 32];

    __syncthreads();

    // z prefetch for t = 0.
    float z0 = 0.f, z1 = 0.f, z2 = 0.f, z3 = 0.f;
    if (tid < 128) {
        size_t zb = ((size_t)0 * G4H + hg) * B_ + bg;
        z0 = __ldcs(&g_z0t[zb + (size_t)0 * H_ * B_]);
        z1 = __ldcs(&g_z0t[zb + (size_t)1 * H_ * B_]);
        z2 = __ldcs(&g_z0t[zb + (size_t)2 * H_ * B_]);
        z3 = __ldcs(&g_z0t[zb + (size_t)3 * H_ * B_]);
    }

    for (int t = 0; t < T_; t++) {
        const float4* __restrict__ src4 = (const float4*)g_gh[g][t & 1];
        float* hdst = g_gh[g][(t + 1) & 1];

        // ---- group barrier wait: all 32 group blocks arrived t times ----
        if (t > 0 && tid == 0) {
            unsigned target = 32u * (unsigned)t;
            while (ld_acq(bar) < target) { }
        }
        __syncthreads();

        // ---- per-warp stage of OWN k-slice: 2KB -> duplicated (h,h) pairs ----
        // float4 i covers k = i>>1, b0 = (i&1)*4; u64 base = 4*i.
#pragma unroll
        for (int q = 0; q < 4; q++) {
            int i = 128 * ks + lane + 32 * q;
            float4 v = __ldcg(&src4[i]);
            ulonglong2* d = (ulonglong2*)(hdup + 4 * i);
            d[0] = make_ulonglong2(pack2(v.x, v.x), pack2(v.y, v.y));
            d[1] = make_ulonglong2(pack2(v.z, v.z), pack2(v.w, v.w));
        }
        __syncwarp();

        // ---- compute: 64 k; per k: 1 w-load, 4 broadcast h-loads, 8 FFMA2 ----
        unsigned long long a0 = 0, a1 = 0, a2 = 0, a3 = 0;
        unsigned long long a4 = 0, a5 = 0, a6 = 0, a7 = 0;
        {
            const unsigned long long* wq = Wsu + lane;
            const int k0 = 64 * ks;
#pragma unroll 4
            for (int kk = k0; kk < k0 + 64; kk++) {
                unsigned long long wv = wq[kk * 32];
                const ulonglong2* hq = (const ulonglong2*)(hdup + kk * 8);
                ulonglong2 h01 = hq[0];
                ulonglong2 h23 = hq[1];
                ulonglong2 h45 = hq[2];
                ulonglong2 h67 = hq[3];
                a0 = fma2(h01.x, wv, a0); a1 = fma2(h01.y, wv, a1);
                a2 = fma2(h23.x, wv, a2); a3 = fma2(h23.y, wv, a3);
                a4 = fma2(h45.x, wv, a4); a5 = fma2(h45.y, wv, a5);
                a6 = fma2(h67.x, wv, a6); a7 = fma2(h67.y, wv, a7);
            }
        }

        // ---- publish split-k partials: red[ks][b][lane] ----
        red[ks * 256 + 0 * 32 + lane] = a0;
        red[ks * 256 + 1 * 32 + lane] = a1;
        red[ks * 256 + 2 * 32 + lane] = a2;
        red[ks * 256 + 3 * 32 + lane] = a3;
        red[ks * 256 + 4 * 32 + lane] = a4;
        red[ks * 256 + 5 * 32 + lane] = a5;
        red[ks * 256 + 6 * 32 + lane] = a6;
        red[ks * 256 + 7 * 32 + lane] = a7;
        __syncthreads();

        // ---- reduce + fast gates (epilogue: b = tid>>4, hc = tid&15) ----
        float h = 0.f;
        if (tid < 128) {
            const ulonglong2* rp =
                (const ulonglong2*)(red + eb * 32 + ec * 2);
            unsigned long long aif = pack2(z0, z1);
            unsigned long long ago = pack2(z2, z3);
#pragma unroll
            for (int kq = 0; kq < 8; kq++) {
                ulonglong2 v = rp[kq * 128];   // red + kq*256 (u64) offset
                aif = add2(aif, v.x);
                ago = add2(ago, v.y);
            }
            float2 zif = unpack2(aif);
            float2 zgo = unpack2(ago);

            float ig = sigf(zif.x);
            float fg = sigf(zif.y);
            float gg = tanh_fast(zgo.x);
            float og = sigf(zgo.y);
            c = fg * c + ig * gg;
            h = og * tanh_fast(c);

            __stcg(&hdst[hg * BG + eb], h);    // publish to group h(t+1)
            hout[eb * HC + ec] = h;
        }
        __syncthreads();   // red reads + hout writes complete

        // ---- arrive: our h(t+1) columns are published ----
        if (tid == 0) red_rel_add1(bar);

        // ---- off-critical-path tail: hist + next z prefetch + finals ----
        if (tid < 32) {
            int bq = tid >> 2;                 // local b
            int qq = tid & 3;                  // float4 quarter
            float4 hv4 = *(const float4*)&hout[bq * HC + qq * 4];
            *(float4*)&hist[((size_t)(g * BG + bq) * T_ + t) * H_
                            + j * HC + qq * 4] = hv4;
        }
        if (tid < 128) {
            if (t == T_ - 1) {
                c_fin[(size_t)bg * H_ + hg] = c;
                h_fin[(size_t)bg * H_ + hg] = h;
            } else {
                size_t zb = ((size_t)(t + 1) * G4H + hg) * B_ + bg;
                z0 = __ldcs(&g_z0t[zb + (size_t)0 * H_ * B_]);
                z1 = __ldcs(&g_z0t[zb + (size_t)1 * H_ * B_]);
                z2 = __ldcs(&g_z0t[zb + (size_t)2 * H_ * B_]);
                z3 = __ldcs(&g_z0t[zb + (size_t)3 * H_ * B_]);
            }
        }
    }
}

// ---------------- launch ----------------
extern "C" void kernel_launch(void* const* d_in, const int* in_sizes, int n_in,
                              void* d_out, int out_size) {
    const float* x    = (const float*)d_in[0];
    const float* h0   = (const float*)d_in[1];
    const float* c0   = (const float*)d_in[2];
    const float* Wi   = (const float*)d_in[3];
    const float* Wh   = (const float*)d_in[4];
    const float* bias = (const float*)d_in[5];
    float* out = (float*)d_out;

    // 128KB (Wsu) + 32KB (hdup) + 16KB (red) + 512B (hout) = 180736 B
    const int rec_smem = 512 * 32 * 8 + 512 * 8 * 8 + 8 * 256 * 8 + 128 * 4;
    cudaFuncSetAttribute(lstm_rec, cudaFuncAttributeMaxDynamicSharedMemorySize,
                         rec_smem);

    dim3 ggrid(G4H / 64, (B_ * T_) / 64);
    gemm_xwi<<<ggrid, 256>>>(x, Wi, bias, h0);

    lstm_rec<<<NB, NT, rec_smem>>>(c0, Wh, out);
}

// round 13
// speedup vs baseline: 2.1716x; 1.0248x over previous
#include <cuda_runtime.h>
#include <cstdint>

// Problem constants
constexpr int B_  = 32;
constexpr int T_  = 1024;
constexpr int F_  = 512;
constexpr int H_  = 512;
constexpr int G4H = 2048;   // 4*H

// Recurrence: 4 independent batch groups x 32 blocks.
#define NB 128
#define NT 256
#define NG 4     // groups
#define BG 8     // batch per group
#define HC 16    // h-cols per block

// ---------------- device scratch ----------------
__device__ float g_z0t[(size_t)T_ * G4H * B_];     // [t][gatecol][b]
__device__ float g_gh[NG][2][H_ * BG];             // per-group h ping-pong [k][b]
__device__ unsigned g_rootv[NG * 32];              // per-group barrier counters

// ---------------- f32x2 + sync helpers ----------------
__device__ __forceinline__ unsigned long long pack2(float x, float y) {
    unsigned long long r;
    asm("mov.b64 %0, {%1, %2};" : "=l"(r) : "f"(x), "f"(y));
    return r;
}
__device__ __forceinline__ unsigned long long fma2(unsigned long long a,
                                                   unsigned long long b,
                                                   unsigned long long c) {
    unsigned long long d;
    asm("fma.rn.f32x2 %0, %1, %2, %3;" : "=l"(d) : "l"(a), "l"(b), "l"(c));
    return d;
}
__device__ __forceinline__ unsigned long long add2(unsigned long long a,
                                                   unsigned long long b) {
    unsigned long long d;
    asm("add.rn.f32x2 %0, %1, %2;" : "=l"(d) : "l"(a), "l"(b));
    return d;
}
__device__ __forceinline__ float2 unpack2(unsigned long long v) {
    float2 f;
    asm("mov.b64 {%0, %1}, %2;" : "=f"(f.x), "=f"(f.y) : "l"(v));
    return f;
}
__device__ __forceinline__ unsigned ld_acq(const unsigned* p) {
    unsigned v;
    asm volatile("ld.acquire.gpu.global.u32 %0, [%1];"
                 : "=r"(v) : "l"(p) : "memory");
    return v;
}
__device__ __forceinline__ void red_rel_add1(unsigned* p) {
    asm volatile("red.release.gpu.global.add.u32 [%0], 1;"
                 :: "l"(p) : "memory");
}
__device__ __forceinline__ float sigf(float x) {
    return 1.f / (1.f + __expf(-x));
}
__device__ __forceinline__ float tanh_fast(float x) {
    return 2.f / (1.f + __expf(-2.f * x)) - 1.f;
}

// ---------------- GEMM: 128x64 block tile, 8x4 micro-tile (FFMA2-bound) ----------------
// z0t[t][col][b] = x[b,t,:] @ Wi[:,col] + bias[col]
// M = 32768, K = 512, N = 2048. 256 threads, 2 CTAs/SM, smem ping-pong.
// Per k per thread: 3 LDS.128 + 8 pack + 16 FFMA2 -> issue 27 < rt 32: FMA-bound.
__global__ void __launch_bounds__(256, 2) gemm_xwi(const float* __restrict__ x,
                                                   const float* __restrict__ Wi,
                                                   const float* __restrict__ bias,
                                                   const float* __restrict__ h0) {
    __shared__ float As[2][16][128];   // [buf][k][row]
    __shared__ float Bs[2][16][64];    // [buf][k][col]
    const int tid = threadIdx.x;

    if (blockIdx.x == 0 && blockIdx.y == 0) {
        for (int i = tid; i < NG * H_ * BG; i += 256) {
            int g   = i >> 12;
            int rem = i & 4095;
            int k   = rem >> 3;
            int b   = rem & 7;
            g_gh[g][0][rem] = h0[(size_t)(g * BG + b) * H_ + k];
        }
        if (tid < NG) g_rootv[tid * 32] = 0;
    }

    const int tm = tid >> 4;            // 0..15 -> rows tm*8..+8
    const int tn = tid & 15;            // cols tn*4
    const int row0 = blockIdx.y * 128;
    const int col0 = blockIdx.x * 64;

    unsigned long long acc[8][2] = {};

    const int ar  = tid >> 1;           // 0..127
    const int akq = (tid & 1) * 8;      // 0 or 8
    const int br  = tid >> 4;
    const int bnq = (tid & 15) * 4;

    const float* xp = &x[(size_t)(row0 + ar) * F_ + akq];
    const float* wp = &Wi[(size_t)br * G4H + col0 + bnq];

    float4 av0 = *(const float4*)xp;
    float4 av1 = *(const float4*)(xp + 4);
    float4 bv  = *(const float4*)wp;

    for (int kt = 0; kt < 32; kt++) {
        const int cur = kt & 1;
        As[cur][akq + 0][ar] = av0.x;
        As[cur][akq + 1][ar] = av0.y;
        As[cur][akq + 2][ar] = av0.z;
        As[cur][akq + 3][ar] = av0.w;
        As[cur][akq + 4][ar] = av1.x;
        As[cur][akq + 5][ar] = av1.y;
        As[cur][akq + 6][ar] = av1.z;
        As[cur][akq + 7][ar] = av1.w;
        *(float4*)&Bs[cur][br][bnq] = bv;
        __syncthreads();
        if (kt < 31) {
            av0 = *(const float4*)(xp + (kt + 1) * 16);
            av1 = *(const float4*)(xp + (kt + 1) * 16 + 4);
            bv  = *(const float4*)(wp + (size_t)(kt + 1) * 16 * G4H);
        }
#pragma unroll
        for (int k = 0; k < 16; k++) {
            float4 alo = *(const float4*)&As[cur][k][tm * 8];
            float4 ahi = *(const float4*)&As[cur][k][tm * 8 + 4];
            const unsigned long long* bp =
                (const unsigned long long*)&Bs[cur][k][tn * 4];
            unsigned long long b0 = bp[0], b1 = bp[1];
            unsigned long long p0 = pack2(alo.x, alo.x);
            unsigned long long p1 = pack2(alo.y, alo.y);
            unsigned long long p2 = pack2(alo.z, alo.z);
            unsigned long long p3 = pack2(alo.w, alo.w);
            unsigned long long p4 = pack2(ahi.x, ahi.x);
            unsigned long long p5 = pack2(ahi.y, ahi.y);
            unsigned long long p6 = pack2(ahi.z, ahi.z);
            unsigned long long p7 = pack2(ahi.w, ahi.w);
            acc[0][0] = fma2(p0, b0, acc[0][0]); acc[0][1] = fma2(p0, b1, acc[0][1]);
            acc[1][0] = fma2(p1, b0, acc[1][0]); acc[1][1] = fma2(p1, b1, acc[1][1]);
            acc[2][0] = fma2(p2, b0, acc[2][0]); acc[2][1] = fma2(p2, b1, acc[2][1]);
            acc[3][0] = fma2(p3, b0, acc[3][0]); acc[3][1] = fma2(p3, b1, acc[3][1]);
            acc[4][0] = fma2(p4, b0, acc[4][0]); acc[4][1] = fma2(p4, b1, acc[4][1]);
            acc[5][0] = fma2(p5, b0, acc[5][0]); acc[5][1] = fma2(p5, b1, acc[5][1]);
            acc[6][0] = fma2(p6, b0, acc[6][0]); acc[6][1] = fma2(p6, b1, acc[6][1]);
            acc[7][0] = fma2(p7, b0, acc[7][0]); acc[7][1] = fma2(p7, b1, acc[7][1]);
        }
        __syncthreads();
    }

#pragma unroll
    for (int i = 0; i < 8; i++) {
        int r  = row0 + tm * 8 + i;
        int t  = r & (T_ - 1);
        int bb = r >> 10;
#pragma unroll
        for (int j = 0; j < 2; j++) {
            float2 v = unpack2(acc[i][j]);
            int c0c = col0 + tn * 4 + j * 2;
            g_z0t[((size_t)t * G4H + c0c + 0) * B_ + bb] = v.x + bias[c0c + 0];
            g_z0t[((size_t)t * G4H + c0c + 1) * B_ + bb] = v.y + bias[c0c + 1];
        }
    }
}

// ---------------- recurrence: 4 independent batch groups (R12, validated) ----------------
// Change vs R12: pre-arrive __syncthreads -> bar.sync 1,128 (epilogue warps only).
__global__ void __launch_bounds__(NT, 1) lstm_rec(const float* __restrict__ c0,
                                                  const float* __restrict__ Wh,
                                                  float* __restrict__ out) {
    extern __shared__ unsigned char dsm[];
    unsigned long long* Wsu  = (unsigned long long*)dsm;           // [k*32+hc*2+pr]
    unsigned long long* hdup = Wsu + 512 * 32;                     // [k*8+b] (h,h)
    unsigned long long* red  = hdup + 512 * 8;                     // [ks*256+b*32+lane]
    float* hout = (float*)(red + 8 * 256);                         // [b*16+hc]

    const int tid  = threadIdx.x;
    const int ks   = tid >> 5;                 // warp = k-split
    const int lane = tid & 31;
    const int g    = blockIdx.x & 3;           // group
    const int j    = blockIdx.x >> 2;          // block within group (0..31)

    // Stage this block's Wh slice ONCE: 512 k x 16 hcols x (if),(go) pairs.
    for (int idx = tid; idx < 512 * HC; idx += NT) {
        int k  = idx >> 4;
        int hc = idx & 15;
        int cb = j * HC + hc;
        const float* wr = &Wh[(size_t)k * G4H + cb];
        Wsu[k * 32 + hc * 2 + 0] = pack2(wr[0 * H_], wr[1 * H_]);
        Wsu[k * 32 + hc * 2 + 1] = pack2(wr[2 * H_], wr[3 * H_]);
    }

    // Epilogue-mapped state (tid < 128): b = tid>>4 (0..7), hc = tid&15.
    const int eb = tid >> 4;
    const int ec = tid & 15;
    const int hg = j * HC + ec;                // global h column
    const int bg = g * BG + eb;                // global batch index
    float c = (tid < 128) ? c0[(size_t)bg * H_ + hg] : 0.f;

    float* c_fin = out;
    float* h_fin = out + B_ * H_;
    float* hist  = out + 2 * B_ * H_;          // [b][t][h]

    unsigned* bar = &g_rootv[g * 32];

    __syncthreads();

    // z prefetch for t = 0.
    float z0 = 0.f, z1 = 0.f, z2 = 0.f, z3 = 0.f;
    if (tid < 128) {
        size_t zb = ((size_t)0 * G4H + hg) * B_ + bg;
        z0 = __ldcs(&g_z0t[zb + (size_t)0 * H_ * B_]);
        z1 = __ldcs(&g_z0t[zb + (size_t)1 * H_ * B_]);
        z2 = __ldcs(&g_z0t[zb + (size_t)2 * H_ * B_]);
        z3 = __ldcs(&g_z0t[zb + (size_t)3 * H_ * B_]);
    }

    for (int t = 0; t < T_; t++) {
        const float4* __restrict__ src4 = (const float4*)g_gh[g][t & 1];
        float* hdst = g_gh[g][(t + 1) & 1];

        // ---- group barrier wait: all 32 group blocks arrived t times ----
        if (t > 0 && tid == 0) {
            unsigned target = 32u * (unsigned)t;
            while (ld_acq(bar) < target) { }
        }
        __syncthreads();

        // ---- per-warp stage of OWN k-slice: 2KB -> duplicated (h,h) pairs ----
#pragma unroll
        for (int q = 0; q < 4; q++) {
            int i = 128 * ks + lane + 32 * q;
            float4 v = __ldcg(&src4[i]);
            ulonglong2* d = (ulonglong2*)(hdup + 4 * i);
            d[0] = make_ulonglong2(pack2(v.x, v.x), pack2(v.y, v.y));
            d[1] = make_ulonglong2(pack2(v.z, v.z), pack2(v.w, v.w));
        }
        __syncwarp();

        // ---- compute: 64 k; per k: 1 w-load, 4 broadcast h-loads, 8 FFMA2 ----
        unsigned long long a0 = 0, a1 = 0, a2 = 0, a3 = 0;
        unsigned long long a4 = 0, a5 = 0, a6 = 0, a7 = 0;
        {
            const unsigned long long* wq = Wsu + lane;
            const int k0 = 64 * ks;
#pragma unroll 4
            for (int kk = k0; kk < k0 + 64; kk++) {
                unsigned long long wv = wq[kk * 32];
                const ulonglong2* hq = (const ulonglong2*)(hdup + kk * 8);
                ulonglong2 h01 = hq[0];
                ulonglong2 h23 = hq[1];
                ulonglong2 h45 = hq[2];
                ulonglong2 h67 = hq[3];
                a0 = fma2(h01.x, wv, a0); a1 = fma2(h01.y, wv, a1);
                a2 = fma2(h23.x, wv, a2); a3 = fma2(h23.y, wv, a3);
                a4 = fma2(h45.x, wv, a4); a5 = fma2(h45.y, wv, a5);
                a6 = fma2(h67.x, wv, a6); a7 = fma2(h67.y, wv, a7);
            }
        }

        // ---- publish split-k partials: red[ks][b][lane] ----
        red[ks * 256 + 0 * 32 + lane] = a0;
        red[ks * 256 + 1 * 32 + lane] = a1;
        red[ks * 256 + 2 * 32 + lane] = a2;
        red[ks * 256 + 3 * 32 + lane] = a3;
        red[ks * 256 + 4 * 32 + lane] = a4;
        red[ks * 256 + 5 * 32 + lane] = a5;
        red[ks * 256 + 6 * 32 + lane] = a6;
        red[ks * 256 + 7 * 32 + lane] = a7;
        __syncthreads();

        // ---- reduce + fast gates (epilogue: b = tid>>4, hc = tid&15) ----
        float h = 0.f;
        if (tid < 128) {
            const ulonglong2* rp =
                (const ulonglong2*)(red + eb * 32 + ec * 2);
            unsigned long long aif = pack2(z0, z1);
            unsigned long long ago = pack2(z2, z3);
#pragma unroll
            for (int kq = 0; kq < 8; kq++) {
                ulonglong2 v = rp[kq * 128];   // red + kq*256 (u64) offset
                aif = add2(aif, v.x);
                ago = add2(ago, v.y);
            }
            float2 zif = unpack2(aif);
            float2 zgo = unpack2(ago);

            float ig = sigf(zif.x);
            float fg = sigf(zif.y);
            float gg = tanh_fast(zgo.x);
            float og = sigf(zgo.y);
            c = fg * c + ig * gg;
            h = og * tanh_fast(c);

            __stcg(&hdst[hg * BG + eb], h);    // publish to group h(t+1)
            hout[eb * HC + ec] = h;

            // epilogue-only sync: publishes visible, hout complete.
            // Warps 4-7 are gated by the NEXT top-of-loop __syncthreads
            // (protects hdup/red reuse), so they need not gate the arrive.
            asm volatile("bar.sync 1, 128;" ::: "memory");

            // ---- arrive: our h(t+1) columns are published ----
            if (tid == 0) red_rel_add1(bar);
        }

        // ---- off-critical-path tail: hist + next z prefetch + finals ----
        if (tid < 32) {
            int bq = tid >> 2;                 // local b
            int qq = tid & 3;                  // float4 quarter
            float4 hv4 = *(const float4*)&hout[bq * HC + qq * 4];
            *(float4*)&hist[((size_t)(g * BG + bq) * T_ + t) * H_
                            + j * HC + qq * 4] = hv4;
        }
        if (tid < 128) {
            if (t == T_ - 1) {
                c_fin[(size_t)bg * H_ + hg] = c;
                h_fin[(size_t)bg * H_ + hg] = h;
            } else {
                size_t zb = ((size_t)(t + 1) * G4H + hg) * B_ + bg;
                z0 = __ldcs(&g_z0t[zb + (size_t)0 * H_ * B_]);
                z1 = __ldcs(&g_z0t[zb + (size_t)1 * H_ * B_]);
                z2 = __ldcs(&g_z0t[zb + (size_t)2 * H_ * B_]);
                z3 = __ldcs(&g_z0t[zb + (size_t)3 * H_ * B_]);
            }
        }
    }
}

// ---------------- launch ----------------
extern "C" void kernel_launch(void* const* d_in, const int* in_sizes, int n_in,
                              void* d_out, int out_size) {
    const float* x    = (const float*)d_in[0];
    const float* h0   = (const float*)d_in[1];
    const float* c0   = (const float*)d_in[2];
    const float* Wi   = (const float*)d_in[3];
    const float* Wh   = (const float*)d_in[4];
    const float* bias = (const float*)d_in[5];
    float* out = (float*)d_out;

    // 128KB (Wsu) + 32KB (hdup) + 16KB (red) + 512B (hout) = 180736 B
    const int rec_smem = 512 * 32 * 8 + 512 * 8 * 8 + 8 * 256 * 8 + 128 * 4;
    cudaFuncSetAttribute(lstm_rec, cudaFuncAttributeMaxDynamicSharedMemorySize,
                         rec_smem);

    dim3 ggrid(G4H / 64, (B_ * T_) / 128);
    gemm_xwi<<<ggrid, 256>>>(x, Wi, bias, h0);

    lstm_rec<<<NB, NT, rec_smem>>>(c0, Wh, out);
}

// round 14
// speedup vs baseline: 2.1902x; 1.0086x over previous
#include <cuda_runtime.h>
#include <cstdint>

// Problem constants
constexpr int B_  = 32;
constexpr int T_  = 1024;
constexpr int F_  = 512;
constexpr int H_  = 512;
constexpr int G4H = 2048;   // 4*H

// Recurrence: 4 independent batch groups x 32 blocks.
#define NB 128
#define NT 256
#define NG 4     // groups
#define BG 8     // batch per group
#define HC 16    // h-cols per block

// ---------------- device scratch ----------------
__device__ float g_z0t[(size_t)T_ * G4H * B_];     // [t][gatecol][b]
__device__ float g_gh[NG][2][H_ * BG];             // per-group h ping-pong [k][b]
// Store-slot barrier: one 128B line per group, one u32 slot per block.
__device__ __align__(128) unsigned g_slots[NG][32];

// ---------------- f32x2 + sync helpers ----------------
__device__ __forceinline__ unsigned long long pack2(float x, float y) {
    unsigned long long r;
    asm("mov.b64 %0, {%1, %2};" : "=l"(r) : "f"(x), "f"(y));
    return r;
}
__device__ __forceinline__ unsigned long long fma2(unsigned long long a,
                                                   unsigned long long b,
                                                   unsigned long long c) {
    unsigned long long d;
    asm("fma.rn.f32x2 %0, %1, %2, %3;" : "=l"(d) : "l"(a), "l"(b), "l"(c));
    return d;
}
__device__ __forceinline__ unsigned long long add2(unsigned long long a,
                                                   unsigned long long b) {
    unsigned long long d;
    asm("add.rn.f32x2 %0, %1, %2;" : "=l"(d) : "l"(a), "l"(b));
    return d;
}
__device__ __forceinline__ float2 unpack2(unsigned long long v) {
    float2 f;
    asm("mov.b64 {%0, %1}, %2;" : "=f"(f.x), "=f"(f.y) : "l"(v));
    return f;
}
__device__ __forceinline__ unsigned ld_acq(const unsigned* p) {
    unsigned v;
    asm volatile("ld.acquire.gpu.global.u32 %0, [%1];"
                 : "=r"(v) : "l"(p) : "memory");
    return v;
}
__device__ __forceinline__ void st_rel(unsigned* p, unsigned v) {
    asm volatile("st.release.gpu.global.u32 [%0], %1;"
                 :: "l"(p), "r"(v) : "memory");
}
__device__ __forceinline__ float sigf(float x) {
    return 1.f / (1.f + __expf(-x));
}
__device__ __forceinline__ float tanh_fast(float x) {
    return 2.f / (1.f + __expf(-2.f * x)) - 1.f;
}

// ---------------- GEMM: 128x64 block tile, 8x4 micro-tile (R13, validated) ----------------
__global__ void __launch_bounds__(256, 2) gemm_xwi(const float* __restrict__ x,
                                                   const float* __restrict__ Wi,
                                                   const float* __restrict__ bias,
                                                   const float* __restrict__ h0) {
    __shared__ float As[2][16][128];   // [buf][k][row]
    __shared__ float Bs[2][16][64];    // [buf][k][col]
    const int tid = threadIdx.x;

    if (blockIdx.x == 0 && blockIdx.y == 0) {
        for (int i = tid; i < NG * H_ * BG; i += 256) {
            int g   = i >> 12;
            int rem = i & 4095;
            int k   = rem >> 3;
            int b   = rem & 7;
            g_gh[g][0][rem] = h0[(size_t)(g * BG + b) * H_ + k];
        }
        if (tid < NG * 32) g_slots[tid >> 5][tid & 31] = 0;
    }

    const int tm = tid >> 4;            // 0..15 -> rows tm*8..+8
    const int tn = tid & 15;            // cols tn*4
    const int row0 = blockIdx.y * 128;
    const int col0 = blockIdx.x * 64;

    unsigned long long acc[8][2] = {};

    const int ar  = tid >> 1;           // 0..127
    const int akq = (tid & 1) * 8;      // 0 or 8
    const int br  = tid >> 4;
    const int bnq = (tid & 15) * 4;

    const float* xp = &x[(size_t)(row0 + ar) * F_ + akq];
    const float* wp = &Wi[(size_t)br * G4H + col0 + bnq];

    float4 av0 = *(const float4*)xp;
    float4 av1 = *(const float4*)(xp + 4);
    float4 bv  = *(const float4*)wp;

    for (int kt = 0; kt < 32; kt++) {
        const int cur = kt & 1;
        As[cur][akq + 0][ar] = av0.x;
        As[cur][akq + 1][ar] = av0.y;
        As[cur][akq + 2][ar] = av0.z;
        As[cur][akq + 3][ar] = av0.w;
        As[cur][akq + 4][ar] = av1.x;
        As[cur][akq + 5][ar] = av1.y;
        As[cur][akq + 6][ar] = av1.z;
        As[cur][akq + 7][ar] = av1.w;
        *(float4*)&Bs[cur][br][bnq] = bv;
        __syncthreads();
        if (kt < 31) {
            av0 = *(const float4*)(xp + (kt + 1) * 16);
            av1 = *(const float4*)(xp + (kt + 1) * 16 + 4);
            bv  = *(const float4*)(wp + (size_t)(kt + 1) * 16 * G4H);
        }
#pragma unroll
        for (int k = 0; k < 16; k++) {
            float4 alo = *(const float4*)&As[cur][k][tm * 8];
            float4 ahi = *(const float4*)&As[cur][k][tm * 8 + 4];
            const unsigned long long* bp =
                (const unsigned long long*)&Bs[cur][k][tn * 4];
            unsigned long long b0 = bp[0], b1 = bp[1];
            unsigned long long p0 = pack2(alo.x, alo.x);
            unsigned long long p1 = pack2(alo.y, alo.y);
            unsigned long long p2 = pack2(alo.z, alo.z);
            unsigned long long p3 = pack2(alo.w, alo.w);
            unsigned long long p4 = pack2(ahi.x, ahi.x);
            unsigned long long p5 = pack2(ahi.y, ahi.y);
            unsigned long long p6 = pack2(ahi.z, ahi.z);
            unsigned long long p7 = pack2(ahi.w, ahi.w);
            acc[0][0] = fma2(p0, b0, acc[0][0]); acc[0][1] = fma2(p0, b1, acc[0][1]);
            acc[1][0] = fma2(p1, b0, acc[1][0]); acc[1][1] = fma2(p1, b1, acc[1][1]);
            acc[2][0] = fma2(p2, b0, acc[2][0]); acc[2][1] = fma2(p2, b1, acc[2][1]);
            acc[3][0] = fma2(p3, b0, acc[3][0]); acc[3][1] = fma2(p3, b1, acc[3][1]);
            acc[4][0] = fma2(p4, b0, acc[4][0]); acc[4][1] = fma2(p4, b1, acc[4][1]);
            acc[5][0] = fma2(p5, b0, acc[5][0]); acc[5][1] = fma2(p5, b1, acc[5][1]);
            acc[6][0] = fma2(p6, b0, acc[6][0]); acc[6][1] = fma2(p6, b1, acc[6][1]);
            acc[7][0] = fma2(p7, b0, acc[7][0]); acc[7][1] = fma2(p7, b1, acc[7][1]);
        }
        __syncthreads();
    }

#pragma unroll
    for (int i = 0; i < 8; i++) {
        int r  = row0 + tm * 8 + i;
        int t  = r & (T_ - 1);
        int bb = r >> 10;
#pragma unroll
        for (int j = 0; j < 2; j++) {
            float2 v = unpack2(acc[i][j]);
            int c0c = col0 + tn * 4 + j * 2;
            g_z0t[((size_t)t * G4H + c0c + 0) * B_ + bb] = v.x + bias[c0c + 0];
            g_z0t[((size_t)t * G4H + c0c + 1) * B_ + bb] = v.y + bias[c0c + 1];
        }
    }
}

// ---------------- recurrence: 4 independent batch groups ----------------
// ONLY change vs R13: store-slot barrier (no atomic serialization; parallel
// 32-slot detection by warp 0 via one coalesced 128B line read + __all_sync).
__global__ void __launch_bounds__(NT, 1) lstm_rec(const float* __restrict__ c0,
                                                  const float* __restrict__ Wh,
                                                  float* __restrict__ out) {
    extern __shared__ unsigned char dsm[];
    unsigned long long* Wsu  = (unsigned long long*)dsm;           // [k*32+hc*2+pr]
    unsigned long long* hdup = Wsu + 512 * 32;                     // [k*8+b] (h,h)
    unsigned long long* red  = hdup + 512 * 8;                     // [ks*256+b*32+lane]
    float* hout = (float*)(red + 8 * 256);                         // [b*16+hc]

    const int tid  = threadIdx.x;
    const int ks   = tid >> 5;                 // warp = k-split
    const int lane = tid & 31;
    const int g    = blockIdx.x & 3;           // group
    const int j    = blockIdx.x >> 2;          // block within group (0..31)

    // Stage this block's Wh slice ONCE: 512 k x 16 hcols x (if),(go) pairs.
    for (int idx = tid; idx < 512 * HC; idx += NT) {
        int k  = idx >> 4;
        int hc = idx & 15;
        int cb = j * HC + hc;
        const float* wr = &Wh[(size_t)k * G4H + cb];
        Wsu[k * 32 + hc * 2 + 0] = pack2(wr[0 * H_], wr[1 * H_]);
        Wsu[k * 32 + hc * 2 + 1] = pack2(wr[2 * H_], wr[3 * H_]);
    }

    // Epilogue-mapped state (tid < 128): b = tid>>4 (0..7), hc = tid&15.
    const int eb = tid >> 4;
    const int ec = tid & 15;
    const int hg = j * HC + ec;                // global h column
    const int bg = g * BG + eb;                // global batch index
    float c = (tid < 128) ? c0[(size_t)bg * H_ + hg] : 0.f;

    float* c_fin = out;
    float* h_fin = out + B_ * H_;
    float* hist  = out + 2 * B_ * H_;          // [b][t][h]

    unsigned* slots = g_slots[g];

    __syncthreads();

    // z prefetch for t = 0.
    float z0 = 0.f, z1 = 0.f, z2 = 0.f, z3 = 0.f;
    if (tid < 128) {
        size_t zb = ((size_t)0 * G4H + hg) * B_ + bg;
        z0 = __ldcs(&g_z0t[zb + (size_t)0 * H_ * B_]);
        z1 = __ldcs(&g_z0t[zb + (size_t)1 * H_ * B_]);
        z2 = __ldcs(&g_z0t[zb + (size_t)2 * H_ * B_]);
        z3 = __ldcs(&g_z0t[zb + (size_t)3 * H_ * B_]);
    }

    for (int t = 0; t < T_; t++) {
        const float4* __restrict__ src4 = (const float4*)g_gh[g][t & 1];
        float* hdst = g_gh[g][(t + 1) & 1];

        // ---- store-slot barrier wait: warp 0 checks all 32 slots >= t ----
        if (t > 0) {
            if (tid < 32) {
                const unsigned target = (unsigned)t;
                bool ready;
                do {
                    unsigned v = ld_acq(&slots[tid]);
                    ready = __all_sync(0xffffffffu, v >= target);
                } while (!ready);
            }
            __syncthreads();
        }

        // ---- per-warp stage of OWN k-slice: 2KB -> duplicated (h,h) pairs ----
#pragma unroll
        for (int q = 0; q < 4; q++) {
            int i = 128 * ks + lane + 32 * q;
            float4 v = __ldcg(&src4[i]);
            ulonglong2* d = (ulonglong2*)(hdup + 4 * i);
            d[0] = make_ulonglong2(pack2(v.x, v.x), pack2(v.y, v.y));
            d[1] = make_ulonglong2(pack2(v.z, v.z), pack2(v.w, v.w));
        }
        __syncwarp();

        // ---- compute: 64 k; per k: 1 w-load, 4 broadcast h-loads, 8 FFMA2 ----
        unsigned long long a0 = 0, a1 = 0, a2 = 0, a3 = 0;
        unsigned long long a4 = 0, a5 = 0, a6 = 0, a7 = 0;
        {
            const unsigned long long* wq = Wsu + lane;
            const int k0 = 64 * ks;
#pragma unroll 4
            for (int kk = k0; kk < k0 + 64; kk++) {
                unsigned long long wv = wq[kk * 32];
                const ulonglong2* hq = (const ulonglong2*)(hdup + kk * 8);
                ulonglong2 h01 = hq[0];
                ulonglong2 h23 = hq[1];
                ulonglong2 h45 = hq[2];
                ulonglong2 h67 = hq[3];
                a0 = fma2(h01.x, wv, a0); a1 = fma2(h01.y, wv, a1);
                a2 = fma2(h23.x, wv, a2); a3 = fma2(h23.y, wv, a3);
                a4 = fma2(h45.x, wv, a4); a5 = fma2(h45.y, wv, a5);
                a6 = fma2(h67.x, wv, a6); a7 = fma2(h67.y, wv, a7);
            }
        }

        // ---- publish split-k partials: red[ks][b][lane] ----
        red[ks * 256 + 0 * 32 + lane] = a0;
        red[ks * 256 + 1 * 32 + lane] = a1;
        red[ks * 256 + 2 * 32 + lane] = a2;
        red[ks * 256 + 3 * 32 + lane] = a3;
        red[ks * 256 + 4 * 32 + lane] = a4;
        red[ks * 256 + 5 * 32 + lane] = a5;
        red[ks * 256 + 6 * 32 + lane] = a6;
        red[ks * 256 + 7 * 32 + lane] = a7;
        __syncthreads();

        // ---- reduce + fast gates (epilogue: b = tid>>4, hc = tid&15) ----
        float h = 0.f;
        if (tid < 128) {
            const ulonglong2* rp =
                (const ulonglong2*)(red + eb * 32 + ec * 2);
            unsigned long long aif = pack2(z0, z1);
            unsigned long long ago = pack2(z2, z3);
#pragma unroll
            for (int kq = 0; kq < 8; kq++) {
                ulonglong2 v = rp[kq * 128];   // red + kq*256 (u64) offset
                aif = add2(aif, v.x);
                ago = add2(ago, v.y);
            }
            float2 zif = unpack2(aif);
            float2 zgo = unpack2(ago);

            float ig = sigf(zif.x);
            float fg = sigf(zif.y);
            float gg = tanh_fast(zgo.x);
            float og = sigf(zgo.y);
            c = fg * c + ig * gg;
            h = og * tanh_fast(c);

            __stcg(&hdst[hg * BG + eb], h);    // publish to group h(t+1)
            hout[eb * HC + ec] = h;

            // epilogue-only sync: publishes complete before the release-store.
            asm volatile("bar.sync 1, 128;" ::: "memory");

            // ---- arrive: plain release store to OWN slot (no atomic) ----
            if (tid == 0) st_rel(&slots[j], (unsigned)(t + 1));
        }

        // ---- off-critical-path tail: hist + next z prefetch + finals ----
        if (tid < 32) {
            int bq = tid >> 2;                 // local b
            int qq = tid & 3;                  // float4 quarter
            float4 hv4 = *(const float4*)&hout[bq * HC + qq * 4];
            *(float4*)&hist[((size_t)(g * BG + bq) * T_ + t) * H_
                            + j * HC + qq * 4] = hv4;
        }
        if (tid < 128) {
            if (t == T_ - 1) {
                c_fin[(size_t)bg * H_ + hg] = c;
                h_fin[(size_t)bg * H_ + hg] = h;
            } else {
                size_t zb = ((size_t)(t + 1) * G4H + hg) * B_ + bg;
                z0 = __ldcs(&g_z0t[zb + (size_t)0 * H_ * B_]);
                z1 = __ldcs(&g_z0t[zb + (size_t)1 * H_ * B_]);
                z2 = __ldcs(&g_z0t[zb + (size_t)2 * H_ * B_]);
                z3 = __ldcs(&g_z0t[zb + (size_t)3 * H_ * B_]);
            }
        }
    }
}

// ---------------- launch ----------------
extern "C" void kernel_launch(void* const* d_in, const int* in_sizes, int n_in,
                              void* d_out, int out_size) {
    const float* x    = (const float*)d_in[0];
    const float* h0   = (const float*)d_in[1];
    const float* c0   = (const float*)d_in[2];
    const float* Wi   = (const float*)d_in[3];
    const float* Wh   = (const float*)d_in[4];
    const float* bias = (const float*)d_in[5];
    float* out = (float*)d_out;

    // 128KB (Wsu) + 32KB (hdup) + 16KB (red) + 512B (hout) = 180736 B
    const int rec_smem = 512 * 32 * 8 + 512 * 8 * 8 + 8 * 256 * 8 + 128 * 4;
    cudaFuncSetAttribute(lstm_rec, cudaFuncAttributeMaxDynamicSharedMemorySize,
                         rec_smem);

    dim3 ggrid(G4H / 64, (B_ * T_) / 128);
    gemm_xwi<<<ggrid, 256>>>(x, Wi, bias, h0);

    lstm_rec<<<NB, NT, rec_smem>>>(c0, Wh, out);
}

// round 15
// speedup vs baseline: 2.2440x; 1.0246x over previous
#include <cuda_runtime.h>
#include <cstdint>

// Problem constants
constexpr int B_  = 32;
constexpr int T_  = 1024;
constexpr int F_  = 512;
constexpr int H_  = 512;
constexpr int G4H = 2048;   // 4*H

// Recurrence: 4 independent batch groups x 32 blocks.
#define NB 128
#define NT 256
#define NG 4     // groups
#define BG 8     // batch per group
#define HC 16    // h-cols per block

// ---------------- device scratch ----------------
__device__ float g_z0t[(size_t)T_ * B_ * G4H];     // [t][b][gatecol]  (coalesced writes)
__device__ float g_gh[NG][2][H_ * BG];             // per-group h ping-pong [k][b]
// Store-slot barrier: one 128B line per group, one u32 slot per block.
__device__ __align__(128) unsigned g_slots[NG][32];

// ---------------- f32x2 + sync helpers ----------------
__device__ __forceinline__ unsigned long long pack2(float x, float y) {
    unsigned long long r;
    asm("mov.b64 %0, {%1, %2};" : "=l"(r) : "f"(x), "f"(y));
    return r;
}
__device__ __forceinline__ unsigned long long fma2(unsigned long long a,
                                                   unsigned long long b,
                                                   unsigned long long c) {
    unsigned long long d;
    asm("fma.rn.f32x2 %0, %1, %2, %3;" : "=l"(d) : "l"(a), "l"(b), "l"(c));
    return d;
}
__device__ __forceinline__ unsigned long long add2(unsigned long long a,
                                                   unsigned long long b) {
    unsigned long long d;
    asm("add.rn.f32x2 %0, %1, %2;" : "=l"(d) : "l"(a), "l"(b));
    return d;
}
__device__ __forceinline__ float2 unpack2(unsigned long long v) {
    float2 f;
    asm("mov.b64 {%0, %1}, %2;" : "=f"(f.x), "=f"(f.y) : "l"(v));
    return f;
}
__device__ __forceinline__ unsigned ld_acq(const unsigned* p) {
    unsigned v;
    asm volatile("ld.acquire.gpu.global.u32 %0, [%1];"
                 : "=r"(v) : "l"(p) : "memory");
    return v;
}
__device__ __forceinline__ void st_rel(unsigned* p, unsigned v) {
    asm volatile("st.release.gpu.global.u32 [%0], %1;"
                 :: "l"(p), "r"(v) : "memory");
}
__device__ __forceinline__ float sigf(float x) {
    return 1.f / (1.f + __expf(-x));
}
__device__ __forceinline__ float tanh_fast(float x) {
    return 2.f / (1.f + __expf(-2.f * x)) - 1.f;
}

// ---------------- GEMM: 128x64 block tile, 8x4 micro-tile (R13, validated) ----------------
// ONLY change: z0t layout [t][b][col] -> epilogue stores are coalesced float2
// (was: [t][col][b] -> 4B-per-128B-line scatter, ~8-16x DRAM write amp).
__global__ void __launch_bounds__(256, 2) gemm_xwi(const float* __restrict__ x,
                                                   const float* __restrict__ Wi,
                                                   const float* __restrict__ bias,
                                                   const float* __restrict__ h0) {
    __shared__ float As[2][16][128];   // [buf][k][row]
    __shared__ float Bs[2][16][64];    // [buf][k][col]
    const int tid = threadIdx.x;

    if (blockIdx.x == 0 && blockIdx.y == 0) {
        for (int i = tid; i < NG * H_ * BG; i += 256) {
            int g   = i >> 12;
            int rem = i & 4095;
            int k   = rem >> 3;
            int b   = rem & 7;
            g_gh[g][0][rem] = h0[(size_t)(g * BG + b) * H_ + k];
        }
        if (tid < NG * 32) g_slots[tid >> 5][tid & 31] = 0;
    }

    const int tm = tid >> 4;            // 0..15 -> rows tm*8..+8
    const int tn = tid & 15;            // cols tn*4
    const int row0 = blockIdx.y * 128;
    const int col0 = blockIdx.x * 64;

    unsigned long long acc[8][2] = {};

    const int ar  = tid >> 1;           // 0..127
    const int akq = (tid & 1) * 8;      // 0 or 8
    const int br  = tid >> 4;
    const int bnq = (tid & 15) * 4;

    const float* xp = &x[(size_t)(row0 + ar) * F_ + akq];
    const float* wp = &Wi[(size_t)br * G4H + col0 + bnq];

    float4 av0 = *(const float4*)xp;
    float4 av1 = *(const float4*)(xp + 4);
    float4 bv  = *(const float4*)wp;

    for (int kt = 0; kt < 32; kt++) {
        const int cur = kt & 1;
        As[cur][akq + 0][ar] = av0.x;
        As[cur][akq + 1][ar] = av0.y;
        As[cur][akq + 2][ar] = av0.z;
        As[cur][akq + 3][ar] = av0.w;
        As[cur][akq + 4][ar] = av1.x;
        As[cur][akq + 5][ar] = av1.y;
        As[cur][akq + 6][ar] = av1.z;
        As[cur][akq + 7][ar] = av1.w;
        *(float4*)&Bs[cur][br][bnq] = bv;
        __syncthreads();
        if (kt < 31) {
            av0 = *(const float4*)(xp + (kt + 1) * 16);
            av1 = *(const float4*)(xp + (kt + 1) * 16 + 4);
            bv  = *(const float4*)(wp + (size_t)(kt + 1) * 16 * G4H);
        }
#pragma unroll
        for (int k = 0; k < 16; k++) {
            float4 alo = *(const float4*)&As[cur][k][tm * 8];
            float4 ahi = *(const float4*)&As[cur][k][tm * 8 + 4];
            const unsigned long long* bp =
                (const unsigned long long*)&Bs[cur][k][tn * 4];
            unsigned long long b0 = bp[0], b1 = bp[1];
            unsigned long long p0 = pack2(alo.x, alo.x);
            unsigned long long p1 = pack2(alo.y, alo.y);
            unsigned long long p2 = pack2(alo.z, alo.z);
            unsigned long long p3 = pack2(alo.w, alo.w);
            unsigned long long p4 = pack2(ahi.x, ahi.x);
            unsigned long long p5 = pack2(ahi.y, ahi.y);
            unsigned long long p6 = pack2(ahi.z, ahi.z);
            unsigned long long p7 = pack2(ahi.w, ahi.w);
            acc[0][0] = fma2(p0, b0, acc[0][0]); acc[0][1] = fma2(p0, b1, acc[0][1]);
            acc[1][0] = fma2(p1, b0, acc[1][0]); acc[1][1] = fma2(p1, b1, acc[1][1]);
            acc[2][0] = fma2(p2, b0, acc[2][0]); acc[2][1] = fma2(p2, b1, acc[2][1]);
            acc[3][0] = fma2(p3, b0, acc[3][0]); acc[3][1] = fma2(p3, b1, acc[3][1]);
            acc[4][0] = fma2(p4, b0, acc[4][0]); acc[4][1] = fma2(p4, b1, acc[4][1]);
            acc[5][0] = fma2(p5, b0, acc[5][0]); acc[5][1] = fma2(p5, b1, acc[5][1]);
            acc[6][0] = fma2(p6, b0, acc[6][0]); acc[6][1] = fma2(p6, b1, acc[6][1]);
            acc[7][0] = fma2(p7, b0, acc[7][0]); acc[7][1] = fma2(p7, b1, acc[7][1]);
        }
        __syncthreads();
    }

#pragma unroll
    for (int i = 0; i < 8; i++) {
        int r  = row0 + tm * 8 + i;
        int t  = r & (T_ - 1);
        int bb = r >> 10;
#pragma unroll
        for (int j = 0; j < 2; j++) {
            float2 v = unpack2(acc[i][j]);
            int c0c = col0 + tn * 4 + j * 2;
            float2 o;
            o.x = v.x + bias[c0c + 0];
            o.y = v.y + bias[c0c + 1];
            *(float2*)&g_z0t[((size_t)t * B_ + bb) * G4H + c0c] = o;
        }
    }
}

// ---------------- recurrence: 4 independent batch groups (R14, validated) ----------------
// ONLY change: z0t read indexing follows the new [t][b][gatecol] layout.
__global__ void __launch_bounds__(NT, 1) lstm_rec(const float* __restrict__ c0,
                                                  const float* __restrict__ Wh,
                                                  float* __restrict__ out) {
    extern __shared__ unsigned char dsm[];
    unsigned long long* Wsu  = (unsigned long long*)dsm;           // [k*32+hc*2+pr]
    unsigned long long* hdup = Wsu + 512 * 32;                     // [k*8+b] (h,h)
    unsigned long long* red  = hdup + 512 * 8;                     // [ks*256+b*32+lane]
    float* hout = (float*)(red + 8 * 256);                         // [b*16+hc]

    const int tid  = threadIdx.x;
    const int ks   = tid >> 5;                 // warp = k-split
    const int lane = tid & 31;
    const int g    = blockIdx.x & 3;           // group
    const int j    = blockIdx.x >> 2;          // block within group (0..31)

    // Stage this block's Wh slice ONCE: 512 k x 16 hcols x (if),(go) pairs.
    for (int idx = tid; idx < 512 * HC; idx += NT) {
        int k  = idx >> 4;
        int hc = idx & 15;
        int cb = j * HC + hc;
        const float* wr = &Wh[(size_t)k * G4H + cb];
        Wsu[k * 32 + hc * 2 + 0] = pack2(wr[0 * H_], wr[1 * H_]);
        Wsu[k * 32 + hc * 2 + 1] = pack2(wr[2 * H_], wr[3 * H_]);
    }

    // Epilogue-mapped state (tid < 128): b = tid>>4 (0..7), hc = tid&15.
    const int eb = tid >> 4;
    const int ec = tid & 15;
    const int hg = j * HC + ec;                // global h column
    const int bg = g * BG + eb;                // global batch index
    float c = (tid < 128) ? c0[(size_t)bg * H_ + hg] : 0.f;

    float* c_fin = out;
    float* h_fin = out + B_ * H_;
    float* hist  = out + 2 * B_ * H_;          // [b][t][h]

    unsigned* slots = g_slots[g];

    __syncthreads();

    // z prefetch for t = 0 (new layout: [t][b][gatecol]).
    float z0 = 0.f, z1 = 0.f, z2 = 0.f, z3 = 0.f;
    if (tid < 128) {
        size_t zb = ((size_t)0 * B_ + bg) * G4H + hg;
        z0 = __ldcs(&g_z0t[zb + 0 * H_]);
        z1 = __ldcs(&g_z0t[zb + 1 * H_]);
        z2 = __ldcs(&g_z0t[zb + 2 * H_]);
        z3 = __ldcs(&g_z0t[zb + 3 * H_]);
    }

    for (int t = 0; t < T_; t++) {
        const float4* __restrict__ src4 = (const float4*)g_gh[g][t & 1];
        float* hdst = g_gh[g][(t + 1) & 1];

        // ---- store-slot barrier wait: warp 0 checks all 32 slots >= t ----
        if (t > 0) {
            if (tid < 32) {
                const unsigned target = (unsigned)t;
                bool ready;
                do {
                    unsigned v = ld_acq(&slots[tid]);
                    ready = __all_sync(0xffffffffu, v >= target);
                } while (!ready);
            }
            __syncthreads();
        }

        // ---- per-warp stage of OWN k-slice: 2KB -> duplicated (h,h) pairs ----
#pragma unroll
        for (int q = 0; q < 4; q++) {
            int i = 128 * ks + lane + 32 * q;
            float4 v = __ldcg(&src4[i]);
            ulonglong2* d = (ulonglong2*)(hdup + 4 * i);
            d[0] = make_ulonglong2(pack2(v.x, v.x), pack2(v.y, v.y));
            d[1] = make_ulonglong2(pack2(v.z, v.z), pack2(v.w, v.w));
        }
        __syncwarp();

        // ---- compute: 64 k; per k: 1 w-load, 4 broadcast h-loads, 8 FFMA2 ----
        unsigned long long a0 = 0, a1 = 0, a2 = 0, a3 = 0;
        unsigned long long a4 = 0, a5 = 0, a6 = 0, a7 = 0;
        {
            const unsigned long long* wq = Wsu + lane;
            const int k0 = 64 * ks;
#pragma unroll 4
            for (int kk = k0; kk < k0 + 64; kk++) {
                unsigned long long wv = wq[kk * 32];
                const ulonglong2* hq = (const ulonglong2*)(hdup + kk * 8);
                ulonglong2 h01 = hq[0];
                ulonglong2 h23 = hq[1];
                ulonglong2 h45 = hq[2];
                ulonglong2 h67 = hq[3];
                a0 = fma2(h01.x, wv, a0); a1 = fma2(h01.y, wv, a1);
                a2 = fma2(h23.x, wv, a2); a3 = fma2(h23.y, wv, a3);
                a4 = fma2(h45.x, wv, a4); a5 = fma2(h45.y, wv, a5);
                a6 = fma2(h67.x, wv, a6); a7 = fma2(h67.y, wv, a7);
            }
        }

        // ---- publish split-k partials: red[ks][b][lane] ----
        red[ks * 256 + 0 * 32 + lane] = a0;
        red[ks * 256 + 1 * 32 + lane] = a1;
        red[ks * 256 + 2 * 32 + lane] = a2;
        red[ks * 256 + 3 * 32 + lane] = a3;
        red[ks * 256 + 4 * 32 + lane] = a4;
        red[ks * 256 + 5 * 32 + lane] = a5;
        red[ks * 256 + 6 * 32 + lane] = a6;
        red[ks * 256 + 7 * 32 + lane] = a7;
        __syncthreads();

        // ---- reduce + fast gates (epilogue: b = tid>>4, hc = tid&15) ----
        float h = 0.f;
        if (tid < 128) {
            const ulonglong2* rp =
                (const ulonglong2*)(red + eb * 32 + ec * 2);
            unsigned long long aif = pack2(z0, z1);
            unsigned long long ago = pack2(z2, z3);
#pragma unroll
            for (int kq = 0; kq < 8; kq++) {
                ulonglong2 v = rp[kq * 128];   // red + kq*256 (u64) offset
                aif = add2(aif, v.x);
                ago = add2(ago, v.y);
            }
            float2 zif = unpack2(aif);
            float2 zgo = unpack2(ago);

            float ig = sigf(zif.x);
            float fg = sigf(zif.y);
            float gg = tanh_fast(zgo.x);
            float og = sigf(zgo.y);
            c = fg * c + ig * gg;
            h = og * tanh_fast(c);

            __stcg(&hdst[hg * BG + eb], h);    // publish to group h(t+1)
            hout[eb * HC + ec] = h;

            // epilogue-only sync: publishes complete before the release-store.
            asm volatile("bar.sync 1, 128;" ::: "memory");

            // ---- arrive: plain release store to OWN slot (no atomic) ----
            if (tid == 0) st_rel(&slots[j], (unsigned)(t + 1));
        }

        // ---- off-critical-path tail: hist + next z prefetch + finals ----
        if (tid < 32) {
            int bq = tid >> 2;                 // local b
            int qq = tid & 3;                  // float4 quarter
            float4 hv4 = *(const float4*)&hout[bq * HC + qq * 4];
            *(float4*)&hist[((size_t)(g * BG + bq) * T_ + t) * H_
                            + j * HC + qq * 4] = hv4;
        }
        if (tid < 128) {
            if (t == T_ - 1) {
                c_fin[(size_t)bg * H_ + hg] = c;
                h_fin[(size_t)bg * H_ + hg] = h;
            } else {
                size_t zb = ((size_t)(t + 1) * B_ + bg) * G4H + hg;
                z0 = __ldcs(&g_z0t[zb + 0 * H_]);
                z1 = __ldcs(&g_z0t[zb + 1 * H_]);
                z2 = __ldcs(&g_z0t[zb + 2 * H_]);
                z3 = __ldcs(&g_z0t[zb + 3 * H_]);
            }
        }
    }
}

// ---------------- launch ----------------
extern "C" void kernel_launch(void* const* d_in, const int* in_sizes, int n_in,
                              void* d_out, int out_size) {
    const float* x    = (const float*)d_in[0];
    const float* h0   = (const float*)d_in[1];
    const float* c0   = (const float*)d_in[2];
    const float* Wi   = (const float*)d_in[3];
    const float* Wh   = (const float*)d_in[4];
    const float* bias = (const float*)d_in[5];
    float* out = (float*)d_out;

    // 128KB (Wsu) + 32KB (hdup) + 16KB (red) + 512B (hout) = 180736 B
    const int rec_smem = 512 * 32 * 8 + 512 * 8 * 8 + 8 * 256 * 8 + 128 * 4;
    cudaFuncSetAttribute(lstm_rec, cudaFuncAttributeMaxDynamicSharedMemorySize,
                         rec_smem);

    dim3 ggrid(G4H / 64, (B_ * T_) / 128);
    gemm_xwi<<<ggrid, 256>>>(x, Wi, bias, h0);

    lstm_rec<<<NB, NT, rec_smem>>>(c0, Wh, out);
}